// round 1
// baseline (speedup 1.0000x reference)
#include <cuda_runtime.h>
#include <cuda_bf16.h>

// Problem dims (fixed by the reference)
#define BB   2
#define SS   1024
#define DD   1024
#define HH   2048
#define EE   8
#define KK   2
#define NPAIR (BB*SS*KK)   // 4096 (token, k-slot) pairs
#define MAXR  NPAIR        // worst-case rows per expert

// ---------------- scratch (static device globals; no allocation) -------------
__device__ int   g_cnt[EE];
__device__ int   g_tok [EE * MAXR];   // token index per bucketed row
__device__ int   g_pair[EE * MAXR];   // global pair id per bucketed row
__device__ float g_hidden[(size_t)NPAIR * HH];  // 32 MB: gelu(x @ K^T) per pair
__device__ float g_scr   [(size_t)NPAIR * DD];  // 16 MB: per-pair output rows

// ---------------- small kernels ----------------------------------------------
__global__ void zero_cnt_kernel() {
    if (threadIdx.x < EE) g_cnt[threadIdx.x] = 0;
}

__global__ void bucket_kernel(const int* __restrict__ eidx) {
    int p = blockIdx.x * blockDim.x + threadIdx.x;
    if (p >= NPAIR) return;
    int token = p / KK;
    int e = eidx[p];                       // in [0, EE)
    int pos = atomicAdd(&g_cnt[e], 1);
    g_tok [e * MAXR + pos] = token;
    g_pair[e * MAXR + pos] = p;
}

__device__ __forceinline__ float gelu_tanh(float v) {
    // jax.nn.gelu approximate=True: 0.5*v*(1+tanh(sqrt(2/pi)*(v+0.044715*v^3)))
    const float c = 0.7978845608028654f;
    float t = tanhf(c * (v + 0.044715f * v * v * v));
    return 0.5f * v * (1.0f + t);
}

// ---------------- grouped TN GEMM (gathered A rows, scattered O rows) --------
// C[i][n] = sum_k A[gather[i]][k] * B_e[n][k]
//   GEMM1 (DOGELU=1): A = x (gather by token), B = keys[e],  O = g_hidden (scatter by pair), NDIM=HH, KDIM=DD
//   GEMM2 (DOGELU=0): A = g_hidden (gather by pair), B = values[e], O = g_scr (scatter by pair), NDIM=DD, KDIM=HH
template<int NDIM, int KDIM, bool DOGELU>
__global__ void __launch_bounds__(256, 2) moe_gemm_kernel(
    const float* __restrict__ Aparam,   // x for GEMM1 (ignored for GEMM2)
    const float* __restrict__ Bfull)    // keys or values, per-expert stride NDIM*KDIM
{
    const int e      = blockIdx.z;
    const int n_rows = g_cnt[e];
    const int row0   = blockIdx.y * 128;
    if (row0 >= n_rows) return;
    const int col0   = blockIdx.x * 128;

    const float* Abase = DOGELU ? Aparam : g_hidden;
    float*       Obase = DOGELU ? g_hidden : g_scr;
    const int* gat = (DOGELU ? g_tok : g_pair) + e * MAXR;
    const int* pr  = g_pair + e * MAXR;
    const float* Bmat = Bfull + (size_t)e * NDIM * KDIM;

    __shared__ float As[16][132];   // [k][m], +4 pad
    __shared__ float Bs[16][132];   // [k][n], +4 pad

    const int tid = threadIdx.x;

    // Per-thread load slots: 2 float4 loads per tile for A, 2 for B.
    const float* aSrc[2]; int aRow[2], aC4[2];
    const float* bSrc[2]; int bRow[2], bC4[2];
#pragma unroll
    for (int s = 0; s < 2; s++) {
        int idx = tid + s * 256;
        int r  = idx >> 2;        // 0..127
        int c4 = idx & 3;         // 0..3 (float4 slot within 16-wide K strip)
        aRow[s] = r; aC4[s] = c4;
        int grow = row0 + r;
        aSrc[s] = (grow < n_rows) ? (Abase + (size_t)gat[grow] * KDIM + c4 * 4) : nullptr;
        bRow[s] = r; bC4[s] = c4;
        bSrc[s] = Bmat + (size_t)(col0 + r) * KDIM + c4 * 4;
    }

    float acc[8][8];
#pragma unroll
    for (int i = 0; i < 8; i++)
#pragma unroll
        for (int j = 0; j < 8; j++) acc[i][j] = 0.0f;

    const int tRow = (tid >> 4) * 8;   // 0..120
    const int tCol = (tid & 15) * 8;   // 0..120

    for (int k0 = 0; k0 < KDIM; k0 += 16) {
#pragma unroll
        for (int s = 0; s < 2; s++) {
            float4 va = aSrc[s] ? *reinterpret_cast<const float4*>(aSrc[s] + k0)
                                : make_float4(0.f, 0.f, 0.f, 0.f);
            As[aC4[s]*4 + 0][aRow[s]] = va.x;
            As[aC4[s]*4 + 1][aRow[s]] = va.y;
            As[aC4[s]*4 + 2][aRow[s]] = va.z;
            As[aC4[s]*4 + 3][aRow[s]] = va.w;
            float4 vb = *reinterpret_cast<const float4*>(bSrc[s] + k0);
            Bs[bC4[s]*4 + 0][bRow[s]] = vb.x;
            Bs[bC4[s]*4 + 1][bRow[s]] = vb.y;
            Bs[bC4[s]*4 + 2][bRow[s]] = vb.z;
            Bs[bC4[s]*4 + 3][bRow[s]] = vb.w;
        }
        __syncthreads();

#pragma unroll
        for (int k = 0; k < 16; k++) {
            float ra[8], rb[8];
            *reinterpret_cast<float4*>(&ra[0]) = *reinterpret_cast<const float4*>(&As[k][tRow]);
            *reinterpret_cast<float4*>(&ra[4]) = *reinterpret_cast<const float4*>(&As[k][tRow + 4]);
            *reinterpret_cast<float4*>(&rb[0]) = *reinterpret_cast<const float4*>(&Bs[k][tCol]);
            *reinterpret_cast<float4*>(&rb[4]) = *reinterpret_cast<const float4*>(&Bs[k][tCol + 4]);
#pragma unroll
            for (int i = 0; i < 8; i++)
#pragma unroll
                for (int j = 0; j < 8; j++)
                    acc[i][j] = fmaf(ra[i], rb[j], acc[i][j]);
        }
        __syncthreads();
    }

    // Epilogue: scatter rows by pair id (coalesced along n within a row).
#pragma unroll
    for (int i = 0; i < 8; i++) {
        int grow = row0 + tRow + i;
        if (grow >= n_rows) continue;
        float* dst = Obase + (size_t)pr[grow] * NDIM + col0 + tCol;
        float o[8];
#pragma unroll
        for (int j = 0; j < 8; j++) {
            float v = acc[i][j];
            o[j] = DOGELU ? gelu_tanh(v) : v;
        }
        *reinterpret_cast<float4*>(dst)     = *reinterpret_cast<const float4*>(&o[0]);
        *reinterpret_cast<float4*>(dst + 4) = *reinterpret_cast<const float4*>(&o[4]);
    }
}

// ---------------- weighted combine of the K=2 pair rows ----------------------
__global__ void combine_kernel(const float* __restrict__ w, float* __restrict__ out) {
    int idx = blockIdx.x * blockDim.x + threadIdx.x;     // over (B*S*D)/4 float4s
    const int total4 = (BB * SS * DD) / 4;
    if (idx >= total4) return;
    int t  = idx / (DD / 4);
    int d4 = idx % (DD / 4);
    float w0 = w[t * KK + 0];
    float w1 = w[t * KK + 1];
    float4 a = reinterpret_cast<const float4*>(g_scr + (size_t)(t * KK + 0) * DD)[d4];
    float4 b = reinterpret_cast<const float4*>(g_scr + (size_t)(t * KK + 1) * DD)[d4];
    float4 r;
    r.x = w0 * a.x + w1 * b.x;
    r.y = w0 * a.y + w1 * b.y;
    r.z = w0 * a.z + w1 * b.z;
    r.w = w0 * a.w + w1 * b.w;
    reinterpret_cast<float4*>(out)[idx] = r;
}

// ---------------- entry point -------------------------------------------------
extern "C" void kernel_launch(void* const* d_in, const int* in_sizes, int n_in,
                              void* d_out, int out_size) {
    const float* x      = (const float*)d_in[0];   // [B,S,D]
    const float* keys   = (const float*)d_in[1];   // [E,H,D]
    const float* values = (const float*)d_in[2];   // [E,D,H]
    const int*   eidx   = (const int*)  d_in[3];   // [B,S,K]
    const float* ew     = (const float*)d_in[4];   // [B,S,K]
    float* out = (float*)d_out;                    // [B,S,D]

    zero_cnt_kernel<<<1, 32>>>();
    bucket_kernel<<<(NPAIR + 255) / 256, 256>>>(eidx);

    // GEMM1: hidden = gelu(x_gathered @ keys^T) ; N=H, K=D
    dim3 g1(HH / 128, MAXR / 128, EE);   // (16, 32, 8) — empty row tiles exit early
    moe_gemm_kernel<HH, DD, true><<<g1, 256>>>(x, keys);

    // GEMM2: scr = hidden @ values^T ; N=D, K=H
    dim3 g2(DD / 128, MAXR / 128, EE);   // (8, 32, 8)
    moe_gemm_kernel<DD, HH, false><<<g2, 256>>>(x /*unused*/, values);

    // out = w0 * scr[pair0] + w1 * scr[pair1]
    const int total4 = (BB * SS * DD) / 4;
    combine_kernel<<<(total4 + 255) / 256, 256>>>(ew, out);
}

// round 3
// speedup vs baseline: 2.5305x; 2.5305x over previous
#include <cuda_runtime.h>
#include <cuda_bf16.h>
#include <cstdint>

// Problem dims (fixed by the reference)
#define BB   2
#define SS   1024
#define DD   1024
#define HH   2048
#define EE   8
#define KK   2
#define NPAIR (BB*SS*KK)   // 4096 (token, k-slot) pairs
#define MAXR  NPAIR

// ---------------- scratch (static device globals; no allocation) -------------
__device__ int   g_cnt[EE];
__device__ int   g_tok [EE * MAXR];
__device__ int   g_pair[EE * MAXR];
__device__ __nv_bfloat16 g_xhi[(size_t)BB * SS * DD];
__device__ __nv_bfloat16 g_xlo[(size_t)BB * SS * DD];
__device__ __nv_bfloat16 g_khi[(size_t)EE * HH * DD];
__device__ __nv_bfloat16 g_klo[(size_t)EE * HH * DD];
__device__ __nv_bfloat16 g_vhi[(size_t)EE * DD * HH];
__device__ __nv_bfloat16 g_vlo[(size_t)EE * DD * HH];
__device__ __nv_bfloat16 g_hhi[(size_t)NPAIR * HH];
__device__ __nv_bfloat16 g_hlo[(size_t)NPAIR * HH];
__device__ float g_scr[(size_t)NPAIR * DD];

// ---------------- PTX helpers (sm_80-class only; no 'a'-gated features) ------
__device__ __forceinline__ uint32_t smem_u32(const void* p) {
    uint32_t a;
    asm("{ .reg .u64 t; cvta.to.shared.u64 t, %1; cvt.u32.u64 %0, t; }" : "=r"(a) : "l"(p));
    return a;
}
__device__ __forceinline__ void cp_async16(uint32_t dst, const void* src, bool valid) {
    int sz = valid ? 16 : 0;
    asm volatile("cp.async.cg.shared.global [%0], [%1], 16, %2;" :: "r"(dst), "l"(src), "r"(sz) : "memory");
}
#define CP_COMMIT() asm volatile("cp.async.commit_group;" ::: "memory")
#define CP_WAIT(N)  asm volatile("cp.async.wait_group %0;" :: "n"(N) : "memory")

__device__ __forceinline__ void ldsm4(uint32_t (&r)[4], uint32_t addr) {
    asm volatile("ldmatrix.sync.aligned.m8n8.x4.shared.b16 {%0,%1,%2,%3}, [%4];"
                 : "=r"(r[0]), "=r"(r[1]), "=r"(r[2]), "=r"(r[3]) : "r"(addr));
}
__device__ __forceinline__ void mma16816(float (&d)[4], const uint32_t (&a)[4],
                                         uint32_t b0, uint32_t b1) {
    asm volatile(
        "mma.sync.aligned.m16n8k16.row.col.f32.bf16.bf16.f32 "
        "{%0,%1,%2,%3}, {%4,%5,%6,%7}, {%8,%9}, {%0,%1,%2,%3};"
        : "+f"(d[0]), "+f"(d[1]), "+f"(d[2]), "+f"(d[3])
        : "r"(a[0]), "r"(a[1]), "r"(a[2]), "r"(a[3]), "r"(b0), "r"(b1));
}
__device__ __forceinline__ uint32_t sw128(uint32_t off) { return off ^ ((off >> 3) & 0x70); }

// ---------------- small kernels ----------------------------------------------
__global__ void zero_cnt_kernel() { if (threadIdx.x < EE) g_cnt[threadIdx.x] = 0; }

__global__ void bucket_kernel(const int* __restrict__ eidx) {
    int p = blockIdx.x * blockDim.x + threadIdx.x;
    if (p >= NPAIR) return;
    int token = p / KK;
    int e = eidx[p];
    int pos = atomicAdd(&g_cnt[e], 1);
    g_tok [e * MAXR + pos] = token;
    g_pair[e * MAXR + pos] = p;
}

__device__ __forceinline__ float gelu_tanh(float v) {
    const float c = 0.7978845608028654f;
    float t = tanhf(c * (v + 0.044715f * v * v * v));
    return 0.5f * v * (1.0f + t);
}

// fp32 -> bf16 (hi, lo) split for x, keys, values in one pass
__global__ void split_all_kernel(const float* __restrict__ x,
                                 const float* __restrict__ keys,
                                 const float* __restrict__ values) {
    const int XN4 = BB * SS * DD / 4;
    const int KN4 = EE * HH * DD / 4;
    const int VN4 = EE * DD * HH / 4;
    int i = blockIdx.x * blockDim.x + threadIdx.x;
    const float4* src; __nv_bfloat16 *hi, *lo; int j;
    if (i < XN4)             { src = (const float4*)x;      hi = g_xhi; lo = g_xlo; j = i; }
    else if (i < XN4 + KN4)  { src = (const float4*)keys;   hi = g_khi; lo = g_klo; j = i - XN4; }
    else if (i < XN4+KN4+VN4){ src = (const float4*)values; hi = g_vhi; lo = g_vlo; j = i - XN4 - KN4; }
    else return;
    float4 v = src[j];
    __nv_bfloat16 h0 = __float2bfloat16(v.x), h1 = __float2bfloat16(v.y);
    __nv_bfloat16 h2 = __float2bfloat16(v.z), h3 = __float2bfloat16(v.w);
    __nv_bfloat16 l0 = __float2bfloat16(v.x - __bfloat162float(h0));
    __nv_bfloat16 l1 = __float2bfloat16(v.y - __bfloat162float(h1));
    __nv_bfloat16 l2 = __float2bfloat16(v.z - __bfloat162float(h2));
    __nv_bfloat16 l3 = __float2bfloat16(v.w - __bfloat162float(h3));
    reinterpret_cast<__nv_bfloat162*>(hi)[2*j]   = __nv_bfloat162(h0, h1);
    reinterpret_cast<__nv_bfloat162*>(hi)[2*j+1] = __nv_bfloat162(h2, h3);
    reinterpret_cast<__nv_bfloat162*>(lo)[2*j]   = __nv_bfloat162(l0, l1);
    reinterpret_cast<__nv_bfloat162*>(lo)[2*j+1] = __nv_bfloat162(l2, l3);
}

// ---------------- HMMA grouped GEMM (mma.sync bf16, 3-term split) -------------
// C[i][n] = sum_k A[gat[i]][k] * B_e[n][k], fp32 accum via hi*hi + hi*lo + lo*hi
// Tiles: CTA 128x128, BK=64, 2-stage cp.async, SW128 swizzle, 8 warps (4m x 2n),
// warp tile 32x64 (2 m16 x 8 n8 fragments), 48 HMMA per warp per k16.
#define TILE_B   16384                 // one 128x64 bf16 tile
#define STAGE_B  (4 * TILE_B)          // Ahi, Alo, Bhi, Blo
#define SMEM_REQ (2 * STAGE_B)         // 128 KB

template<int NDIM, int KDIM, bool DOGELU>
__global__ void __launch_bounds__(256, 1) moe_hmma_kernel() {
    const int e      = blockIdx.z;
    const int n_rows = g_cnt[e];
    const int row0   = blockIdx.y * 128;
    if (row0 >= n_rows) return;
    const int col0   = blockIdx.x * 128;

    const int* gat = (DOGELU ? g_tok : g_pair) + e * MAXR;
    const int* pr  = g_pair + e * MAXR;
    const __nv_bfloat16* Ahi = DOGELU ? g_xhi : g_hhi;
    const __nv_bfloat16* Alo = DOGELU ? g_xlo : g_hlo;
    const __nv_bfloat16* Bhi = (DOGELU ? g_khi : g_vhi) + (size_t)e * NDIM * KDIM;
    const __nv_bfloat16* Blo = (DOGELU ? g_klo : g_vlo) + (size_t)e * NDIM * KDIM;

    extern __shared__ char smem_dyn[];
    const uint32_t smB = smem_u32(smem_dyn);

    const int tid  = threadIdx.x;
    const int wid  = tid >> 5, lane = tid & 31;
    const int wm   = wid & 3;          // warp row   -> rows [wm*32, wm*32+32)
    const int wn   = wid >> 2;         // warp col   -> cols [wn*64, wn*64+64)

    // -------- cp.async assignment: 4 rows/thread (stride 32), chunk c = tid&7
    const int c8 = tid & 7;            // 16B chunk within 128B row
    int  arow[4]; bool aok[4]; int aid[4]; int brow[4];
    uint32_t dsto[4];
#pragma unroll
    for (int s = 0; s < 4; s++) {
        int r = (tid >> 3) + 32 * s;
        arow[s] = r;
        dsto[s] = sw128((uint32_t)(r * 128 + c8 * 16));
        int grow = row0 + r;
        aok[s] = grow < n_rows;
        aid[s] = aok[s] ? gat[grow] : 0;
        brow[s] = col0 + r;
    }

    auto issue = [&](int stage, int buf) {
        size_t k0 = (size_t)stage * 64 + c8 * 8;   // element offset in K
        uint32_t b = smB + (uint32_t)buf * STAGE_B;
#pragma unroll
        for (int s = 0; s < 4; s++) {
            size_t ae = (size_t)aid[s]  * KDIM + k0;
            size_t be = (size_t)brow[s] * KDIM + k0;
            cp_async16(b + 0*TILE_B + dsto[s], Ahi + ae, aok[s]);
            cp_async16(b + 1*TILE_B + dsto[s], Alo + ae, aok[s]);
            cp_async16(b + 2*TILE_B + dsto[s], Bhi + be, true);
            cp_async16(b + 3*TILE_B + dsto[s], Blo + be, true);
        }
        CP_COMMIT();
    };

    float acc[2][8][4];
#pragma unroll
    for (int mt = 0; mt < 2; mt++)
#pragma unroll
        for (int nt = 0; nt < 8; nt++)
#pragma unroll
            for (int r = 0; r < 4; r++) acc[mt][nt][r] = 0.0f;

    // ldmatrix per-thread row/byte precompute
    const int aRowL  = wm * 32 + (lane & 15);            // + mt*16
    const int aKHalf = (lane >> 4) * 16;                 // byte offset of k-half
    const int bRowL  = wn * 64 + ((lane >> 4) << 3) + (lane & 7);  // + ng*16
    const int bKHalf = ((lane >> 3) & 1) * 16;

    const int NS = KDIM / 64;
    issue(0, 0);

    for (int i = 0; i < NS; i++) {
        const int buf = i & 1;
        if (i + 1 < NS) { issue(i + 1, buf ^ 1); CP_WAIT(1); }
        else            { CP_WAIT(0); }
        __syncthreads();

        const uint32_t bb   = smB + (uint32_t)buf * STAGE_B;
        const uint32_t sAh = bb, sAl = bb + TILE_B, sBh = bb + 2*TILE_B, sBl = bb + 3*TILE_B;

#pragma unroll
        for (int ks = 0; ks < 4; ks++) {
            const int kb = ks * 32;    // byte offset of k16 step (16 elems * 2B)
            uint32_t ah[2][4], al[2][4], bh[4][4], bl[4][4];
#pragma unroll
            for (int mt = 0; mt < 2; mt++) {
                uint32_t off = sw128((uint32_t)((aRowL + mt*16) * 128 + kb + aKHalf));
                ldsm4(ah[mt], sAh + off);
                ldsm4(al[mt], sAl + off);
            }
#pragma unroll
            for (int ng = 0; ng < 4; ng++) {
                uint32_t off = sw128((uint32_t)((bRowL + ng*16) * 128 + kb + bKHalf));
                ldsm4(bh[ng], sBh + off);
                ldsm4(bl[ng], sBl + off);
            }
#pragma unroll
            for (int mt = 0; mt < 2; mt++)
#pragma unroll
                for (int nt = 0; nt < 8; nt++) {
                    const int ng = nt >> 1, h = (nt & 1) * 2;
                    mma16816(acc[mt][nt], ah[mt], bh[ng][h], bh[ng][h+1]);
                    mma16816(acc[mt][nt], ah[mt], bl[ng][h], bl[ng][h+1]);
                    mma16816(acc[mt][nt], al[mt], bh[ng][h], bh[ng][h+1]);
                }
        }
        __syncthreads();
    }

    // -------- epilogue: fragment rows -> scattered global rows
    // frag (mt, nt) regs: (c0,c1) at (row= wm*32+mt*16+lane/4,      col= wn*64+nt*8+(lane&3)*2)
    //                     (c2,c3) at (row+8, same col)
    int prid[2][2];
#pragma unroll
    for (int mt = 0; mt < 2; mt++)
#pragma unroll
        for (int hf = 0; hf < 2; hf++) {
            int grow = row0 + wm*32 + mt*16 + (lane >> 2) + hf*8;
            prid[mt][hf] = (grow < n_rows) ? pr[grow] : -1;
        }

#pragma unroll
    for (int mt = 0; mt < 2; mt++)
#pragma unroll
        for (int hf = 0; hf < 2; hf++) {
            const int pid = prid[mt][hf];
            if (pid < 0) continue;
#pragma unroll
            for (int nt = 0; nt < 8; nt++) {
                const int colg = col0 + wn*64 + nt*8 + (lane & 3)*2;
                float v0 = acc[mt][nt][hf*2 + 0];
                float v1 = acc[mt][nt][hf*2 + 1];
                if (DOGELU) {
                    v0 = gelu_tanh(v0); v1 = gelu_tanh(v1);
                    __nv_bfloat16 h0 = __float2bfloat16(v0), h1 = __float2bfloat16(v1);
                    __nv_bfloat16 l0 = __float2bfloat16(v0 - __bfloat162float(h0));
                    __nv_bfloat16 l1 = __float2bfloat16(v1 - __bfloat162float(h1));
                    *reinterpret_cast<__nv_bfloat162*>(g_hhi + (size_t)pid * NDIM + colg) = __nv_bfloat162(h0, h1);
                    *reinterpret_cast<__nv_bfloat162*>(g_hlo + (size_t)pid * NDIM + colg) = __nv_bfloat162(l0, l1);
                } else {
                    *reinterpret_cast<float2*>(g_scr + (size_t)pid * NDIM + colg) = make_float2(v0, v1);
                }
            }
        }
}

// ---------------- weighted combine --------------------------------------------
__global__ void combine_kernel(const float* __restrict__ w, float* __restrict__ out) {
    int idx = blockIdx.x * blockDim.x + threadIdx.x;
    const int total4 = (BB * SS * DD) / 4;
    if (idx >= total4) return;
    int t  = idx / (DD / 4);
    int d4 = idx % (DD / 4);
    float w0 = w[t * KK + 0];
    float w1 = w[t * KK + 1];
    float4 a = reinterpret_cast<const float4*>(g_scr + (size_t)(t * KK + 0) * DD)[d4];
    float4 b = reinterpret_cast<const float4*>(g_scr + (size_t)(t * KK + 1) * DD)[d4];
    float4 r;
    r.x = w0 * a.x + w1 * b.x;
    r.y = w0 * a.y + w1 * b.y;
    r.z = w0 * a.z + w1 * b.z;
    r.w = w0 * a.w + w1 * b.w;
    reinterpret_cast<float4*>(out)[idx] = r;
}

// ---------------- entry point ---------------------------------------------------
extern "C" void kernel_launch(void* const* d_in, const int* in_sizes, int n_in,
                              void* d_out, int out_size) {
    const float* x      = (const float*)d_in[0];   // [B,S,D]
    const float* keys   = (const float*)d_in[1];   // [E,H,D]
    const float* values = (const float*)d_in[2];   // [E,D,H]
    const int*   eidx   = (const int*)  d_in[3];   // [B,S,K]
    const float* ew     = (const float*)d_in[4];   // [B,S,K]
    float* out = (float*)d_out;                    // [B,S,D]

    cudaFuncSetAttribute((const void*)moe_hmma_kernel<HH, DD, true>,
                         cudaFuncAttributeMaxDynamicSharedMemorySize, SMEM_REQ);
    cudaFuncSetAttribute((const void*)moe_hmma_kernel<DD, HH, false>,
                         cudaFuncAttributeMaxDynamicSharedMemorySize, SMEM_REQ);

    zero_cnt_kernel<<<1, 32>>>();
    bucket_kernel<<<(NPAIR + 255) / 256, 256>>>(eidx);

    const int total4 = (BB*SS*DD + EE*HH*DD + EE*DD*HH) / 4;
    split_all_kernel<<<(total4 + 255) / 256, 256>>>(x, keys, values);

    dim3 g1(HH / 128, MAXR / 128, EE);   // (16, 32, 8)
    moe_hmma_kernel<HH, DD, true><<<g1, 256, SMEM_REQ>>>();

    dim3 g2(DD / 128, MAXR / 128, EE);   // (8, 32, 8)
    moe_hmma_kernel<DD, HH, false><<<g2, 256, SMEM_REQ>>>();

    const int out4 = (BB * SS * DD) / 4;
    combine_kernel<<<(out4 + 255) / 256, 256>>>(ew, out);
}

// round 4
// speedup vs baseline: 5.3495x; 2.1140x over previous
#include <cuda_runtime.h>
#include <cuda_fp16.h>
#include <cstdint>

// Problem dims (fixed by the reference)
#define BB   2
#define SS   1024
#define DD   1024
#define HH   2048
#define EE   8
#define KK   2
#define NPAIR (BB*SS*KK)   // 4096 (token, k-slot) pairs
#define MAXR  NPAIR

// ---------------- scratch (static device globals; no allocation) -------------
__device__ int   g_cnt[EE];
__device__ int   g_tok [EE * MAXR];
__device__ int   g_pair[EE * MAXR];
__device__ __half g_xh[(size_t)BB * SS * DD];
__device__ __half g_kh[(size_t)EE * HH * DD];
__device__ __half g_vh[(size_t)EE * DD * HH];
__device__ __half g_hid[(size_t)NPAIR * HH];
__device__ float  g_scr[(size_t)NPAIR * DD];

// ---------------- PTX helpers (sm_80-class only) ------------------------------
__device__ __forceinline__ uint32_t smem_u32(const void* p) {
    uint32_t a;
    asm("{ .reg .u64 t; cvta.to.shared.u64 t, %1; cvt.u32.u64 %0, t; }" : "=r"(a) : "l"(p));
    return a;
}
__device__ __forceinline__ void cp_async16(uint32_t dst, const void* src, bool valid) {
    int sz = valid ? 16 : 0;
    asm volatile("cp.async.cg.shared.global [%0], [%1], 16, %2;" :: "r"(dst), "l"(src), "r"(sz) : "memory");
}
#define CP_COMMIT() asm volatile("cp.async.commit_group;" ::: "memory")
#define CP_WAIT(N)  asm volatile("cp.async.wait_group %0;" :: "n"(N) : "memory")

__device__ __forceinline__ void ldsm4(uint32_t (&r)[4], uint32_t addr) {
    asm volatile("ldmatrix.sync.aligned.m8n8.x4.shared.b16 {%0,%1,%2,%3}, [%4];"
                 : "=r"(r[0]), "=r"(r[1]), "=r"(r[2]), "=r"(r[3]) : "r"(addr));
}
__device__ __forceinline__ void mma16816(float (&d)[4], const uint32_t (&a)[4],
                                         uint32_t b0, uint32_t b1) {
    asm volatile(
        "mma.sync.aligned.m16n8k16.row.col.f32.f16.f16.f32 "
        "{%0,%1,%2,%3}, {%4,%5,%6,%7}, {%8,%9}, {%0,%1,%2,%3};"
        : "+f"(d[0]), "+f"(d[1]), "+f"(d[2]), "+f"(d[3])
        : "r"(a[0]), "r"(a[1]), "r"(a[2]), "r"(a[3]), "r"(b0), "r"(b1));
}
__device__ __forceinline__ uint32_t sw128(uint32_t off) { return off ^ ((off >> 3) & 0x70); }

// ---------------- small kernels ----------------------------------------------
__global__ void zero_cnt_kernel() { if (threadIdx.x < EE) g_cnt[threadIdx.x] = 0; }

__global__ void bucket_kernel(const int* __restrict__ eidx) {
    int p = blockIdx.x * blockDim.x + threadIdx.x;
    if (p >= NPAIR) return;
    int token = p / KK;
    int e = eidx[p];
    int pos = atomicAdd(&g_cnt[e], 1);
    g_tok [e * MAXR + pos] = token;
    g_pair[e * MAXR + pos] = p;
}

__device__ __forceinline__ float gelu_tanh(float v) {
    const float c = 0.7978845608028654f;
    float t = tanhf(c * (v + 0.044715f * v * v * v));
    return 0.5f * v * (1.0f + t);
}

// fp32 -> fp16 convert for x, keys, values in one streaming pass
__global__ void cvt_all_kernel(const float* __restrict__ x,
                               const float* __restrict__ keys,
                               const float* __restrict__ values) {
    const int XN4 = BB * SS * DD / 4;
    const int KN4 = EE * HH * DD / 4;
    const int VN4 = EE * DD * HH / 4;
    int i = blockIdx.x * blockDim.x + threadIdx.x;
    const float4* src; __half* dst; int j;
    if (i < XN4)              { src = (const float4*)x;      dst = g_xh; j = i; }
    else if (i < XN4 + KN4)   { src = (const float4*)keys;   dst = g_kh; j = i - XN4; }
    else if (i < XN4+KN4+VN4) { src = (const float4*)values; dst = g_vh; j = i - XN4 - KN4; }
    else return;
    float4 v = src[j];
    __half2* d2 = reinterpret_cast<__half2*>(dst);
    d2[2*j]   = __floats2half2_rn(v.x, v.y);
    d2[2*j+1] = __floats2half2_rn(v.z, v.w);
}

// ---------------- HMMA grouped GEMM (fp16 single-pass, fp32 accum) ------------
// C[i][n] = sum_k A[gat[i]][k] * B_e[n][k]
// CTA tile 128(M) x 256(N), BK=64, 3-stage cp.async ring, 512 threads,
// warps 4m x 4n, warp tile 32x64 (2 m16 x 8 n8 fragments).
#define A_TILE_B 16384                 // 128 x 64 fp16
#define B_TILE_B 32768                 // 256 x 64 fp16
#define STAGE_B  (A_TILE_B + B_TILE_B) // 48 KB
#define NSTAGE   3
#define SMEM_REQ (NSTAGE * STAGE_B)    // 144 KB

template<int NDIM, int KDIM, bool DOGELU>
__global__ void __launch_bounds__(512, 1) moe_hmma_kernel() {
    const int e      = blockIdx.z;
    const int n_rows = g_cnt[e];
    const int row0   = blockIdx.y * 128;
    if (row0 >= n_rows) return;
    const int col0   = blockIdx.x * 256;

    const int* gat = (DOGELU ? g_tok : g_pair) + e * MAXR;
    const int* pr  = g_pair + e * MAXR;
    const __half* A = DOGELU ? g_xh : g_hid;
    const __half* B = (DOGELU ? g_kh : g_vh) + (size_t)e * NDIM * KDIM;

    extern __shared__ char smem_dyn[];
    const uint32_t smB = smem_u32(smem_dyn);

    const int tid  = threadIdx.x;
    const int wid  = tid >> 5, lane = tid & 31;
    const int wm   = wid & 3;          // warp row -> rows [wm*32, +32)
    const int wn   = wid >> 2;         // warp col -> cols [wn*64, +64)

    // -------- cp.async: thread handles 2 A rows + 4 B rows, chunk c8 = tid&7
    const int c8    = tid & 7;
    const int rbase = tid >> 3;        // 0..63
    bool aok[2]; int aid[2]; uint32_t adst[2];
    int brow[4];  uint32_t bdst[4];
#pragma unroll
    for (int s = 0; s < 2; s++) {
        int r = rbase + 64 * s;
        adst[s] = sw128((uint32_t)(r * 128 + c8 * 16));
        int grow = row0 + r;
        aok[s] = grow < n_rows;
        aid[s] = aok[s] ? gat[grow] : 0;
    }
#pragma unroll
    for (int s = 0; s < 4; s++) {
        int r = rbase + 64 * s;
        bdst[s] = A_TILE_B + sw128((uint32_t)(r * 128 + c8 * 16));
        brow[s] = col0 + r;
    }

    auto issue = [&](int stage, int buf) {
        size_t k0 = (size_t)stage * 64 + c8 * 8;
        uint32_t b = smB + (uint32_t)buf * STAGE_B;
#pragma unroll
        for (int s = 0; s < 2; s++)
            cp_async16(b + adst[s], A + (size_t)aid[s] * KDIM + k0, aok[s]);
#pragma unroll
        for (int s = 0; s < 4; s++)
            cp_async16(b + bdst[s], B + (size_t)brow[s] * KDIM + k0, true);
        CP_COMMIT();
    };

    float acc[2][8][4];
#pragma unroll
    for (int mt = 0; mt < 2; mt++)
#pragma unroll
        for (int nt = 0; nt < 8; nt++)
#pragma unroll
            for (int r = 0; r < 4; r++) acc[mt][nt][r] = 0.0f;

    // ldmatrix per-thread addressing
    const int aRowL  = wm * 32 + (lane & 15);
    const int aKHalf = (lane >> 4) * 16;                         // bytes
    const int bRowL  = wn * 64 + ((lane >> 4) << 3) + (lane & 7);
    const int bKHalf = ((lane >> 3) & 1) * 16;                   // bytes

    const int NS = KDIM / 64;
    issue(0, 0);
    issue(1, 1);

    for (int i = 0; i < NS; i++) {
        const int buf = i % NSTAGE;
        if (i + 2 < NS) { issue(i + 2, (i + 2) % NSTAGE); CP_WAIT(2); }
        else if (i + 1 < NS) { CP_WAIT(1); }
        else { CP_WAIT(0); }
        __syncthreads();

        const uint32_t bb = smB + (uint32_t)buf * STAGE_B;
        const uint32_t sA = bb, sB = bb + A_TILE_B;

#pragma unroll
        for (int ks = 0; ks < 4; ks++) {
            const int kb = ks * 32;    // k16 step in bytes
            uint32_t ah[2][4], bh[4][4];
#pragma unroll
            for (int mt = 0; mt < 2; mt++)
                ldsm4(ah[mt], sA + sw128((uint32_t)((aRowL + mt*16) * 128 + kb + aKHalf)));
#pragma unroll
            for (int ng = 0; ng < 4; ng++)
                ldsm4(bh[ng], sB + sw128((uint32_t)((bRowL + ng*16) * 128 + kb + bKHalf)));
#pragma unroll
            for (int mt = 0; mt < 2; mt++)
#pragma unroll
                for (int nt = 0; nt < 8; nt++) {
                    const int ng = nt >> 1, h = (nt & 1) * 2;
                    mma16816(acc[mt][nt], ah[mt], bh[ng][h], bh[ng][h+1]);
                }
        }
        __syncthreads();
    }

    // -------- epilogue: fragment rows -> scattered global rows
    int prid[2][2];
#pragma unroll
    for (int mt = 0; mt < 2; mt++)
#pragma unroll
        for (int hf = 0; hf < 2; hf++) {
            int grow = row0 + wm*32 + mt*16 + (lane >> 2) + hf*8;
            prid[mt][hf] = (grow < n_rows) ? pr[grow] : -1;
        }

#pragma unroll
    for (int mt = 0; mt < 2; mt++)
#pragma unroll
        for (int hf = 0; hf < 2; hf++) {
            const int pid = prid[mt][hf];
            if (pid < 0) continue;
#pragma unroll
            for (int nt = 0; nt < 8; nt++) {
                const int colg = col0 + wn*64 + nt*8 + (lane & 3)*2;
                float v0 = acc[mt][nt][hf*2 + 0];
                float v1 = acc[mt][nt][hf*2 + 1];
                if (DOGELU) {
                    v0 = gelu_tanh(v0); v1 = gelu_tanh(v1);
                    *reinterpret_cast<__half2*>(g_hid + (size_t)pid * NDIM + colg) =
                        __floats2half2_rn(v0, v1);
                } else {
                    *reinterpret_cast<float2*>(g_scr + (size_t)pid * NDIM + colg) =
                        make_float2(v0, v1);
                }
            }
        }
}

// ---------------- weighted combine --------------------------------------------
__global__ void combine_kernel(const float* __restrict__ w, float* __restrict__ out) {
    int idx = blockIdx.x * blockDim.x + threadIdx.x;
    const int total4 = (BB * SS * DD) / 4;
    if (idx >= total4) return;
    int t  = idx / (DD / 4);
    int d4 = idx % (DD / 4);
    float w0 = w[t * KK + 0];
    float w1 = w[t * KK + 1];
    float4 a = reinterpret_cast<const float4*>(g_scr + (size_t)(t * KK + 0) * DD)[d4];
    float4 b = reinterpret_cast<const float4*>(g_scr + (size_t)(t * KK + 1) * DD)[d4];
    float4 r;
    r.x = w0 * a.x + w1 * b.x;
    r.y = w0 * a.y + w1 * b.y;
    r.z = w0 * a.z + w1 * b.z;
    r.w = w0 * a.w + w1 * b.w;
    reinterpret_cast<float4*>(out)[idx] = r;
}

// ---------------- entry point ---------------------------------------------------
extern "C" void kernel_launch(void* const* d_in, const int* in_sizes, int n_in,
                              void* d_out, int out_size) {
    const float* x      = (const float*)d_in[0];   // [B,S,D]
    const float* keys   = (const float*)d_in[1];   // [E,H,D]
    const float* values = (const float*)d_in[2];   // [E,D,H]
    const int*   eidx   = (const int*)  d_in[3];   // [B,S,K]
    const float* ew     = (const float*)d_in[4];   // [B,S,K]
    float* out = (float*)d_out;                    // [B,S,D]

    cudaFuncSetAttribute((const void*)moe_hmma_kernel<HH, DD, true>,
                         cudaFuncAttributeMaxDynamicSharedMemorySize, SMEM_REQ);
    cudaFuncSetAttribute((const void*)moe_hmma_kernel<DD, HH, false>,
                         cudaFuncAttributeMaxDynamicSharedMemorySize, SMEM_REQ);

    zero_cnt_kernel<<<1, 32>>>();
    bucket_kernel<<<(NPAIR + 255) / 256, 256>>>(eidx);

    const int total4 = (BB*SS*DD + EE*HH*DD + EE*DD*HH) / 4;
    cvt_all_kernel<<<(total4 + 255) / 256, 256>>>(x, keys, values);

    dim3 g1(HH / 256, MAXR / 128, EE);   // (8, 32, 8)
    moe_hmma_kernel<HH, DD, true><<<g1, 512, SMEM_REQ>>>();

    dim3 g2(DD / 256, MAXR / 128, EE);   // (4, 32, 8)
    moe_hmma_kernel<DD, HH, false><<<g2, 512, SMEM_REQ>>>();

    const int out4 = (BB * SS * DD) / 4;
    combine_kernel<<<(out4 + 255) / 256, 256>>>(ew, out);
}

// round 5
// speedup vs baseline: 5.4162x; 1.0125x over previous
#include <cuda_runtime.h>
#include <cuda_fp16.h>
#include <cstdint>

// Problem dims (fixed by the reference)
#define BB   2
#define SS   1024
#define DD   1024
#define HH   2048
#define EE   8
#define KK   2
#define NPAIR (BB*SS*KK)   // 4096 (token, k-slot) pairs
#define MAXR  NPAIR

// ---------------- scratch (static device globals; no allocation) -------------
__device__ int   g_cnt[EE];
__device__ int   g_tok [EE * MAXR];
__device__ int   g_pair[EE * MAXR];
__device__ __half g_xh[(size_t)BB * SS * DD];
__device__ __half g_kh[(size_t)EE * HH * DD];
__device__ __half g_vh[(size_t)EE * DD * HH];
__device__ __half g_hid[(size_t)NPAIR * HH];
__device__ float  g_scr[(size_t)NPAIR * DD];

// ---------------- PTX helpers (sm_80-class only) ------------------------------
__device__ __forceinline__ uint32_t smem_u32(const void* p) {
    uint32_t a;
    asm("{ .reg .u64 t; cvta.to.shared.u64 t, %1; cvt.u32.u64 %0, t; }" : "=r"(a) : "l"(p));
    return a;
}
__device__ __forceinline__ void cp_async16(uint32_t dst, const void* src, bool valid) {
    int sz = valid ? 16 : 0;
    asm volatile("cp.async.cg.shared.global [%0], [%1], 16, %2;" :: "r"(dst), "l"(src), "r"(sz) : "memory");
}
#define CP_COMMIT() asm volatile("cp.async.commit_group;" ::: "memory")
#define CP_WAIT(N)  asm volatile("cp.async.wait_group %0;" :: "n"(N) : "memory")

__device__ __forceinline__ void ldsm4(uint32_t (&r)[4], uint32_t addr) {
    asm volatile("ldmatrix.sync.aligned.m8n8.x4.shared.b16 {%0,%1,%2,%3}, [%4];"
                 : "=r"(r[0]), "=r"(r[1]), "=r"(r[2]), "=r"(r[3]) : "r"(addr));
}
__device__ __forceinline__ void mma16816(float (&d)[4], const uint32_t (&a)[4],
                                         uint32_t b0, uint32_t b1) {
    asm volatile(
        "mma.sync.aligned.m16n8k16.row.col.f32.f16.f16.f32 "
        "{%0,%1,%2,%3}, {%4,%5,%6,%7}, {%8,%9}, {%0,%1,%2,%3};"
        : "+f"(d[0]), "+f"(d[1]), "+f"(d[2]), "+f"(d[3])
        : "r"(a[0]), "r"(a[1]), "r"(a[2]), "r"(a[3]), "r"(b0), "r"(b1));
}
__device__ __forceinline__ uint32_t sw128(uint32_t off) { return off ^ ((off >> 3) & 0x70); }

// ---------------- small kernels ----------------------------------------------
__global__ void zero_cnt_kernel() { if (threadIdx.x < EE) g_cnt[threadIdx.x] = 0; }

__global__ void bucket_kernel(const int* __restrict__ eidx) {
    int p = blockIdx.x * blockDim.x + threadIdx.x;
    if (p >= NPAIR) return;
    int token = p / KK;
    int e = eidx[p];
    int pos = atomicAdd(&g_cnt[e], 1);
    g_tok [e * MAXR + pos] = token;
    g_pair[e * MAXR + pos] = p;
}

__device__ __forceinline__ float gelu_tanh(float v) {
    const float c = 0.7978845608028654f;
    float t = tanhf(c * (v + 0.044715f * v * v * v));
    return 0.5f * v * (1.0f + t);
}

// fp32 -> fp16 convert for x, keys, values in one streaming pass
__global__ void cvt_all_kernel(const float* __restrict__ x,
                               const float* __restrict__ keys,
                               const float* __restrict__ values) {
    const int XN4 = BB * SS * DD / 4;
    const int KN4 = EE * HH * DD / 4;
    const int VN4 = EE * DD * HH / 4;
    int i = blockIdx.x * blockDim.x + threadIdx.x;
    const float4* src; __half* dst; int j;
    if (i < XN4)              { src = (const float4*)x;      dst = g_xh; j = i; }
    else if (i < XN4 + KN4)   { src = (const float4*)keys;   dst = g_kh; j = i - XN4; }
    else if (i < XN4+KN4+VN4) { src = (const float4*)values; dst = g_vh; j = i - XN4 - KN4; }
    else return;
    float4 v = src[j];
    __half2* d2 = reinterpret_cast<__half2*>(dst);
    d2[2*j]   = __floats2half2_rn(v.x, v.y);
    d2[2*j+1] = __floats2half2_rn(v.z, v.w);
}

// ---------------- HMMA grouped GEMM (fp16 single-pass, fp32 accum) ------------
// C[i][n] = sum_k A[gat[i]][k] * B_e[n][k]
// CTA tile 128(M) x 128(N), BK=64, 3-stage cp.async ring, 256 threads,
// 2 CTAs/SM; warps 4m x 2n, warp tile 32x64; ONE barrier per k-iteration.
#define A_TILE_B 16384                 // 128 x 64 fp16
#define B_TILE_B 16384                 // 128 x 64 fp16
#define STAGE_B  (A_TILE_B + B_TILE_B) // 32 KB
#define NSTAGE   3
#define SMEM_REQ (NSTAGE * STAGE_B)    // 96 KB -> 2 CTAs/SM

template<int NDIM, int KDIM, bool DOGELU>
__global__ void __launch_bounds__(256, 2) moe_hmma_kernel() {
    const int e      = blockIdx.z;
    const int n_rows = g_cnt[e];
    const int row0   = blockIdx.y * 128;
    if (row0 >= n_rows) return;
    const int col0   = blockIdx.x * 128;

    const int* gat = (DOGELU ? g_tok : g_pair) + e * MAXR;
    const int* pr  = g_pair + e * MAXR;
    const __half* A = DOGELU ? g_xh : g_hid;
    const __half* B = (DOGELU ? g_kh : g_vh) + (size_t)e * NDIM * KDIM;

    extern __shared__ char smem_dyn[];
    const uint32_t smB = smem_u32(smem_dyn);

    const int tid  = threadIdx.x;
    const int wid  = tid >> 5, lane = tid & 31;
    const int wm   = wid & 3;          // warp row -> rows [wm*32, +32)
    const int wn   = wid >> 2;         // warp col -> cols [wn*64, +64)

    // -------- cp.async: thread handles 4 A rows + 4 B rows, chunk c8 = tid&7
    const int c8    = tid & 7;
    const int rbase = tid >> 3;        // 0..31
    bool aok[4]; int aid[4]; uint32_t adst[4];
    int brow[4];  uint32_t bdst[4];
#pragma unroll
    for (int s = 0; s < 4; s++) {
        int r = rbase + 32 * s;
        uint32_t sw = sw128((uint32_t)(r * 128 + c8 * 16));
        adst[s] = sw;
        bdst[s] = A_TILE_B + sw;
        int grow = row0 + r;
        aok[s] = grow < n_rows;
        aid[s] = aok[s] ? gat[grow] : 0;
        brow[s] = col0 + r;
    }

    auto issue = [&](int stage, int buf) {
        size_t k0 = (size_t)stage * 64 + c8 * 8;
        uint32_t b = smB + (uint32_t)buf * STAGE_B;
#pragma unroll
        for (int s = 0; s < 4; s++)
            cp_async16(b + adst[s], A + (size_t)aid[s] * KDIM + k0, aok[s]);
#pragma unroll
        for (int s = 0; s < 4; s++)
            cp_async16(b + bdst[s], B + (size_t)brow[s] * KDIM + k0, true);
        CP_COMMIT();
    };

    float acc[2][8][4];
#pragma unroll
    for (int mt = 0; mt < 2; mt++)
#pragma unroll
        for (int nt = 0; nt < 8; nt++)
#pragma unroll
            for (int r = 0; r < 4; r++) acc[mt][nt][r] = 0.0f;

    // ldmatrix per-thread addressing
    const int aRowL  = wm * 32 + (lane & 15);
    const int aKHalf = (lane >> 4) * 16;                         // bytes
    const int bRowL  = wn * 64 + ((lane >> 4) << 3) + (lane & 7);
    const int bKHalf = ((lane >> 3) & 1) * 16;                   // bytes

    const int NS = KDIM / 64;
    issue(0, 0);
    issue(1, 1);

    for (int i = 0; i < NS; i++) {
        const int buf = i % NSTAGE;
        if (i + 1 < NS) { CP_WAIT(1); } else { CP_WAIT(0); }
        __syncthreads();
        // Safe: buffer (i+2)%3 == (i-1)%3 was last read in iter i-1; all warps
        // passed this barrier only after finishing iter i-1's mma (program order).
        if (i + 2 < NS) issue(i + 2, (i + 2) % NSTAGE);

        const uint32_t bb = smB + (uint32_t)buf * STAGE_B;
        const uint32_t sA = bb, sB = bb + A_TILE_B;

#pragma unroll
        for (int ks = 0; ks < 4; ks++) {
            const int kb = ks * 32;    // k16 step in bytes
            uint32_t ah[2][4], bh[4][4];
#pragma unroll
            for (int mt = 0; mt < 2; mt++)
                ldsm4(ah[mt], sA + sw128((uint32_t)((aRowL + mt*16) * 128 + kb + aKHalf)));
#pragma unroll
            for (int ng = 0; ng < 4; ng++)
                ldsm4(bh[ng], sB + sw128((uint32_t)((bRowL + ng*16) * 128 + kb + bKHalf)));
#pragma unroll
            for (int mt = 0; mt < 2; mt++)
#pragma unroll
                for (int nt = 0; nt < 8; nt++) {
                    const int ng = nt >> 1, h = (nt & 1) * 2;
                    mma16816(acc[mt][nt], ah[mt], bh[ng][h], bh[ng][h+1]);
                }
        }
    }

    // -------- epilogue: fragment rows -> scattered global rows
    int prid[2][2];
#pragma unroll
    for (int mt = 0; mt < 2; mt++)
#pragma unroll
        for (int hf = 0; hf < 2; hf++) {
            int grow = row0 + wm*32 + mt*16 + (lane >> 2) + hf*8;
            prid[mt][hf] = (grow < n_rows) ? pr[grow] : -1;
        }

#pragma unroll
    for (int mt = 0; mt < 2; mt++)
#pragma unroll
        for (int hf = 0; hf < 2; hf++) {
            const int pid = prid[mt][hf];
            if (pid < 0) continue;
#pragma unroll
            for (int nt = 0; nt < 8; nt++) {
                const int colg = col0 + wn*64 + nt*8 + (lane & 3)*2;
                float v0 = acc[mt][nt][hf*2 + 0];
                float v1 = acc[mt][nt][hf*2 + 1];
                if (DOGELU) {
                    v0 = gelu_tanh(v0); v1 = gelu_tanh(v1);
                    *reinterpret_cast<__half2*>(g_hid + (size_t)pid * NDIM + colg) =
                        __floats2half2_rn(v0, v1);
                } else {
                    *reinterpret_cast<float2*>(g_scr + (size_t)pid * NDIM + colg) =
                        make_float2(v0, v1);
                }
            }
        }
}

// ---------------- weighted combine --------------------------------------------
__global__ void combine_kernel(const float* __restrict__ w, float* __restrict__ out) {
    int idx = blockIdx.x * blockDim.x + threadIdx.x;
    const int total4 = (BB * SS * DD) / 4;
    if (idx >= total4) return;
    int t  = idx / (DD / 4);
    int d4 = idx % (DD / 4);
    float w0 = w[t * KK + 0];
    float w1 = w[t * KK + 1];
    float4 a = reinterpret_cast<const float4*>(g_scr + (size_t)(t * KK + 0) * DD)[d4];
    float4 b = reinterpret_cast<const float4*>(g_scr + (size_t)(t * KK + 1) * DD)[d4];
    float4 r;
    r.x = w0 * a.x + w1 * b.x;
    r.y = w0 * a.y + w1 * b.y;
    r.z = w0 * a.z + w1 * b.z;
    r.w = w0 * a.w + w1 * b.w;
    reinterpret_cast<float4*>(out)[idx] = r;
}

// ---------------- entry point ---------------------------------------------------
extern "C" void kernel_launch(void* const* d_in, const int* in_sizes, int n_in,
                              void* d_out, int out_size) {
    const float* x      = (const float*)d_in[0];   // [B,S,D]
    const float* keys   = (const float*)d_in[1];   // [E,H,D]
    const float* values = (const float*)d_in[2];   // [E,D,H]
    const int*   eidx   = (const int*)  d_in[3];   // [B,S,K]
    const float* ew     = (const float*)d_in[4];   // [B,S,K]
    float* out = (float*)d_out;                    // [B,S,D]

    cudaFuncSetAttribute((const void*)moe_hmma_kernel<HH, DD, true>,
                         cudaFuncAttributeMaxDynamicSharedMemorySize, SMEM_REQ);
    cudaFuncSetAttribute((const void*)moe_hmma_kernel<DD, HH, false>,
                         cudaFuncAttributeMaxDynamicSharedMemorySize, SMEM_REQ);

    zero_cnt_kernel<<<1, 32>>>();
    bucket_kernel<<<(NPAIR + 255) / 256, 256>>>(eidx);

    const int total4 = (BB*SS*DD + EE*HH*DD + EE*DD*HH) / 4;
    cvt_all_kernel<<<(total4 + 255) / 256, 256>>>(x, keys, values);

    dim3 g1(HH / 128, MAXR / 128, EE);   // (16, 32, 8)
    moe_hmma_kernel<HH, DD, true><<<g1, 256, SMEM_REQ>>>();

    dim3 g2(DD / 128, MAXR / 128, EE);   // (8, 32, 8)
    moe_hmma_kernel<DD, HH, false><<<g2, 256, SMEM_REQ>>>();

    const int out4 = (BB * SS * DD) / 4;
    combine_kernel<<<(out4 + 255) / 256, 256>>>(ew, out);
}

// round 6
// speedup vs baseline: 5.5467x; 1.0241x over previous
#include <cuda_runtime.h>
#include <cuda_fp16.h>
#include <cstdint>

// Problem dims (fixed by the reference)
#define BB   2
#define SS   1024
#define DD   1024
#define HH   2048
#define EE   8
#define KK   2
#define NPAIR (BB*SS*KK)   // 4096 (token, k-slot) pairs
#define MAXR  NPAIR

// ---------------- scratch (static device globals; no allocation) -------------
__device__ int   g_cnt[EE];
__device__ int   g_tok [EE * MAXR];
__device__ int   g_pair[EE * MAXR];
__device__ __half g_xh[(size_t)BB * SS * DD];
__device__ __half g_kh[(size_t)EE * HH * DD];
__device__ __half g_vh[(size_t)EE * DD * HH];
__device__ __half g_hid[(size_t)NPAIR * HH];
__device__ float  g_scr[(size_t)NPAIR * DD];

// ---------------- PTX helpers (sm_80-class only) ------------------------------
__device__ __forceinline__ uint32_t smem_u32(const void* p) {
    uint32_t a;
    asm("{ .reg .u64 t; cvta.to.shared.u64 t, %1; cvt.u32.u64 %0, t; }" : "=r"(a) : "l"(p));
    return a;
}
__device__ __forceinline__ void cp_async16(uint32_t dst, const void* src, bool valid) {
    int sz = valid ? 16 : 0;
    asm volatile("cp.async.cg.shared.global [%0], [%1], 16, %2;" :: "r"(dst), "l"(src), "r"(sz) : "memory");
}
#define CP_COMMIT() asm volatile("cp.async.commit_group;" ::: "memory")
#define CP_WAIT(N)  asm volatile("cp.async.wait_group %0;" :: "n"(N) : "memory")

__device__ __forceinline__ void ldsm4(uint32_t (&r)[4], uint32_t addr) {
    asm volatile("ldmatrix.sync.aligned.m8n8.x4.shared.b16 {%0,%1,%2,%3}, [%4];"
                 : "=r"(r[0]), "=r"(r[1]), "=r"(r[2]), "=r"(r[3]) : "r"(addr));
}
__device__ __forceinline__ void mma16816(float (&d)[4], const uint32_t (&a)[4],
                                         uint32_t b0, uint32_t b1) {
    asm volatile(
        "mma.sync.aligned.m16n8k16.row.col.f32.f16.f16.f32 "
        "{%0,%1,%2,%3}, {%4,%5,%6,%7}, {%8,%9}, {%0,%1,%2,%3};"
        : "+f"(d[0]), "+f"(d[1]), "+f"(d[2]), "+f"(d[3])
        : "r"(a[0]), "r"(a[1]), "r"(a[2]), "r"(a[3]), "r"(b0), "r"(b1));
}
__device__ __forceinline__ uint32_t sw128(uint32_t off) { return off ^ ((off >> 3) & 0x70); }

// ---------------- small kernels ----------------------------------------------
__global__ void zero_cnt_kernel() { if (threadIdx.x < EE) g_cnt[threadIdx.x] = 0; }

__global__ void bucket_kernel(const int* __restrict__ eidx) {
    int p = blockIdx.x * blockDim.x + threadIdx.x;
    if (p >= NPAIR) return;
    int token = p / KK;
    int e = eidx[p];
    int pos = atomicAdd(&g_cnt[e], 1);
    g_tok [e * MAXR + pos] = token;
    g_pair[e * MAXR + pos] = p;
}

__device__ __forceinline__ float gelu_tanh(float v) {
    const float c = 0.7978845608028654f;
    float t = tanhf(c * (v + 0.044715f * v * v * v));
    return 0.5f * v * (1.0f + t);
}

// fp32 -> fp16 convert for x, keys, values in one streaming pass
__global__ void cvt_all_kernel(const float* __restrict__ x,
                               const float* __restrict__ keys,
                               const float* __restrict__ values) {
    const int XN4 = BB * SS * DD / 4;
    const int KN4 = EE * HH * DD / 4;
    const int VN4 = EE * DD * HH / 4;
    int i = blockIdx.x * blockDim.x + threadIdx.x;
    const float4* src; __half* dst; int j;
    if (i < XN4)              { src = (const float4*)x;      dst = g_xh; j = i; }
    else if (i < XN4 + KN4)   { src = (const float4*)keys;   dst = g_kh; j = i - XN4; }
    else if (i < XN4+KN4+VN4) { src = (const float4*)values; dst = g_vh; j = i - XN4 - KN4; }
    else return;
    float4 v = src[j];
    __half2* d2 = reinterpret_cast<__half2*>(dst);
    d2[2*j]   = __floats2half2_rn(v.x, v.y);
    d2[2*j+1] = __floats2half2_rn(v.z, v.w);
}

// ---------------- HMMA grouped GEMM (fp16, fp32 accum, reg-pipelined) ---------
// C[i][n] = sum_k A[gat[i]][k] * B_e[n][k]
// CTA tile 128x128, BK=64, 3-stage cp.async ring, 256 threads, 2 CTAs/SM.
// Warps 4m x 2n, warp tile 32x64. Fragments double-buffered in registers:
// k-step ks+1 LDSMs issue before ks MMAs execute.
#define A_TILE_B 16384
#define B_TILE_B 16384
#define STAGE_B  (A_TILE_B + B_TILE_B) // 32 KB
#define NSTAGE   3
#define SMEM_REQ (NSTAGE * STAGE_B)    // 96 KB

template<int NDIM, int KDIM, bool DOGELU>
__global__ void __launch_bounds__(256, 2) moe_hmma_kernel() {
    const int e      = blockIdx.z;
    const int n_rows = g_cnt[e];
    const int row0   = blockIdx.y * 128;
    if (row0 >= n_rows) return;
    const int col0   = blockIdx.x * 128;

    const int* gat = (DOGELU ? g_tok : g_pair) + e * MAXR;
    const int* pr  = g_pair + e * MAXR;
    const __half* A = DOGELU ? g_xh : g_hid;
    const __half* B = (DOGELU ? g_kh : g_vh) + (size_t)e * NDIM * KDIM;

    extern __shared__ char smem_dyn[];
    const uint32_t smB = smem_u32(smem_dyn);

    const int tid  = threadIdx.x;
    const int wid  = tid >> 5, lane = tid & 31;
    const int wm   = wid & 3;
    const int wn   = wid >> 2;

    // -------- cp.async: thread handles 4 A rows + 4 B rows, chunk c8 = tid&7
    const int c8    = tid & 7;
    const int rbase = tid >> 3;        // 0..31
    bool aok[4]; int aid[4]; uint32_t adst[4];
    int brow[4];  uint32_t bdst[4];
#pragma unroll
    for (int s = 0; s < 4; s++) {
        int r = rbase + 32 * s;
        uint32_t sw = sw128((uint32_t)(r * 128 + c8 * 16));
        adst[s] = sw;
        bdst[s] = A_TILE_B + sw;
        int grow = row0 + r;
        aok[s] = grow < n_rows;
        aid[s] = aok[s] ? gat[grow] : 0;
        brow[s] = col0 + r;
    }

    auto issue = [&](int stage, int buf) {
        size_t k0 = (size_t)stage * 64 + c8 * 8;
        uint32_t b = smB + (uint32_t)buf * STAGE_B;
#pragma unroll
        for (int s = 0; s < 4; s++)
            cp_async16(b + adst[s], A + (size_t)aid[s] * KDIM + k0, aok[s]);
#pragma unroll
        for (int s = 0; s < 4; s++)
            cp_async16(b + bdst[s], B + (size_t)brow[s] * KDIM + k0, true);
        CP_COMMIT();
    };

    float acc[2][8][4];
#pragma unroll
    for (int mt = 0; mt < 2; mt++)
#pragma unroll
        for (int nt = 0; nt < 8; nt++)
#pragma unroll
            for (int r = 0; r < 4; r++) acc[mt][nt][r] = 0.0f;

    // ldmatrix per-thread addressing
    const int aRowL  = wm * 32 + (lane & 15);
    const int aKHalf = (lane >> 4) * 16;
    const int bRowL  = wn * 64 + ((lane >> 4) << 3) + (lane & 7);
    const int bKHalf = ((lane >> 3) & 1) * 16;

    // double-buffered fragments
    uint32_t ah[2][2][4], bh[2][4][4];

    auto load_frags = [&](int fb, uint32_t sA, uint32_t sB, int ks) {
        const int kb = ks * 32;
#pragma unroll
        for (int mt = 0; mt < 2; mt++)
            ldsm4(ah[fb][mt], sA + sw128((uint32_t)((aRowL + mt*16) * 128 + kb + aKHalf)));
#pragma unroll
        for (int ng = 0; ng < 4; ng++)
            ldsm4(bh[fb][ng], sB + sw128((uint32_t)((bRowL + ng*16) * 128 + kb + bKHalf)));
    };
    auto do_mma = [&](int fb) {
#pragma unroll
        for (int mt = 0; mt < 2; mt++)
#pragma unroll
            for (int nt = 0; nt < 8; nt++) {
                const int ng = nt >> 1, h = (nt & 1) * 2;
                mma16816(acc[mt][nt], ah[fb][mt], bh[fb][ng][h], bh[fb][ng][h+1]);
            }
    };

    const int NS = KDIM / 64;
    issue(0, 0);
    issue(1, 1);

    for (int i = 0; i < NS; i++) {
        const int buf = i % NSTAGE;
        if (i + 1 < NS) { CP_WAIT(1); } else { CP_WAIT(0); }
        __syncthreads();
        // Safe: buffer (i+2)%3 == (i-1)%3 last read in iter i-1; all warps have
        // finished iter i-1 mma before passing this barrier (program order).
        if (i + 2 < NS) issue(i + 2, (i + 2) % NSTAGE);

        const uint32_t bb = smB + (uint32_t)buf * STAGE_B;
        const uint32_t sA = bb, sB = bb + A_TILE_B;

        load_frags(0, sA, sB, 0);
#pragma unroll
        for (int ks = 0; ks < 4; ks++) {
            if (ks < 3) load_frags((ks + 1) & 1, sA, sB, ks + 1);
            do_mma(ks & 1);
        }
    }

    // -------- epilogue: fragment rows -> scattered global rows
    int prid[2][2];
#pragma unroll
    for (int mt = 0; mt < 2; mt++)
#pragma unroll
        for (int hf = 0; hf < 2; hf++) {
            int grow = row0 + wm*32 + mt*16 + (lane >> 2) + hf*8;
            prid[mt][hf] = (grow < n_rows) ? pr[grow] : -1;
        }

#pragma unroll
    for (int mt = 0; mt < 2; mt++)
#pragma unroll
        for (int hf = 0; hf < 2; hf++) {
            const int pid = prid[mt][hf];
            if (pid < 0) continue;
#pragma unroll
            for (int nt = 0; nt < 8; nt++) {
                const int colg = col0 + wn*64 + nt*8 + (lane & 3)*2;
                float v0 = acc[mt][nt][hf*2 + 0];
                float v1 = acc[mt][nt][hf*2 + 1];
                if (DOGELU) {
                    v0 = gelu_tanh(v0); v1 = gelu_tanh(v1);
                    *reinterpret_cast<__half2*>(g_hid + (size_t)pid * NDIM + colg) =
                        __floats2half2_rn(v0, v1);
                } else {
                    *reinterpret_cast<float2*>(g_scr + (size_t)pid * NDIM + colg) =
                        make_float2(v0, v1);
                }
            }
        }
}

// ---------------- weighted combine --------------------------------------------
__global__ void combine_kernel(const float* __restrict__ w, float* __restrict__ out) {
    int idx = blockIdx.x * blockDim.x + threadIdx.x;
    const int total4 = (BB * SS * DD) / 4;
    if (idx >= total4) return;
    int t  = idx / (DD / 4);
    int d4 = idx % (DD / 4);
    float w0 = w[t * KK + 0];
    float w1 = w[t * KK + 1];
    float4 a = reinterpret_cast<const float4*>(g_scr + (size_t)(t * KK + 0) * DD)[d4];
    float4 b = reinterpret_cast<const float4*>(g_scr + (size_t)(t * KK + 1) * DD)[d4];
    float4 r;
    r.x = w0 * a.x + w1 * b.x;
    r.y = w0 * a.y + w1 * b.y;
    r.z = w0 * a.z + w1 * b.z;
    r.w = w0 * a.w + w1 * b.w;
    reinterpret_cast<float4*>(out)[idx] = r;
}

// ---------------- entry point ---------------------------------------------------
extern "C" void kernel_launch(void* const* d_in, const int* in_sizes, int n_in,
                              void* d_out, int out_size) {
    const float* x      = (const float*)d_in[0];   // [B,S,D]
    const float* keys   = (const float*)d_in[1];   // [E,H,D]
    const float* values = (const float*)d_in[2];   // [E,D,H]
    const int*   eidx   = (const int*)  d_in[3];   // [B,S,K]
    const float* ew     = (const float*)d_in[4];   // [B,S,K]
    float* out = (float*)d_out;                    // [B,S,D]

    cudaFuncSetAttribute((const void*)moe_hmma_kernel<HH, DD, true>,
                         cudaFuncAttributeMaxDynamicSharedMemorySize, SMEM_REQ);
    cudaFuncSetAttribute((const void*)moe_hmma_kernel<DD, HH, false>,
                         cudaFuncAttributeMaxDynamicSharedMemorySize, SMEM_REQ);

    zero_cnt_kernel<<<1, 32>>>();
    bucket_kernel<<<(NPAIR + 255) / 256, 256>>>(eidx);

    const int total4 = (BB*SS*DD + EE*HH*DD + EE*DD*HH) / 4;
    cvt_all_kernel<<<(total4 + 255) / 256, 256>>>(x, keys, values);

    dim3 g1(HH / 128, MAXR / 128, EE);   // (16, 32, 8)
    moe_hmma_kernel<HH, DD, true><<<g1, 256, SMEM_REQ>>>();

    dim3 g2(DD / 128, MAXR / 128, EE);   // (8, 32, 8)
    moe_hmma_kernel<DD, HH, false><<<g2, 256, SMEM_REQ>>>();

    const int out4 = (BB * SS * DD) / 4;
    combine_kernel<<<(out4 + 255) / 256, 256>>>(ew, out);
}